// round 13
// baseline (speedup 1.0000x reference)
#include <cuda_runtime.h>
#include <cstdint>

// SNN: x[B,5] -> L1(32) -> spike(dot>=2) -> L2(32) -> L3(16) -> L4(10) -> spike.
// R8 body (const-port W1, 1 row/thread, direct __ldg x, zero-fill + rare
// scatter, popc gate: sound bound, rel_err==0 across R3-R11) with:
//  - minpop computed inline by warp 0, published at a barrier AFTER layer-1
//  - 256-bit zero-fill stores (320 chunks of 32B = full 2560-float tile; the
//    R12 failure was an 80-vs-320 chunk-count bug, fixed here)
//  - no setup kernel node (only the cW1 memcpy node remains)

__constant__ __align__(16) float cW1[160];

// exact layers 2-4 (rare, ~1e-4 of rows); identical to R1-R11 validated code.
__device__ __noinline__ unsigned rare_path(unsigned mask1,
                                           const float* __restrict__ W2,
                                           const float* __restrict__ W3,
                                           const float* __restrict__ W4)
{
    unsigned mask2 = 0;
    #pragma unroll
    for (int jc = 0; jc < 32; jc += 8) {
        float acc[8] = {0, 0, 0, 0, 0, 0, 0, 0};
        unsigned mm = mask1;
        while (mm) {
            int i = __ffs(mm) - 1; mm &= mm - 1;
            #pragma unroll
            for (int j = 0; j < 8; j++) acc[j] += W2[(jc + j) * 32 + i];
        }
        #pragma unroll
        for (int j = 0; j < 8; j++)
            if (acc[j] >= 2.0f) mask2 |= 1u << (jc + j);
    }
    if (!mask2) return 0;

    unsigned mask3 = 0;
    #pragma unroll
    for (int jc = 0; jc < 16; jc += 8) {
        float acc[8] = {0, 0, 0, 0, 0, 0, 0, 0};
        unsigned mm = mask2;
        while (mm) {
            int i = __ffs(mm) - 1; mm &= mm - 1;
            #pragma unroll
            for (int j = 0; j < 8; j++) acc[j] += W3[(jc + j) * 32 + i];
        }
        #pragma unroll
        for (int j = 0; j < 8; j++)
            if (acc[j] >= 2.0f) mask3 |= 1u << (jc + j);
    }
    if (!mask3) return 0;

    float acc4[10];
    #pragma unroll
    for (int j = 0; j < 10; j++) acc4[j] = 0.0f;
    unsigned mm = mask3;
    while (mm) {
        int i = __ffs(mm) - 1; mm &= mm - 1;
        #pragma unroll
        for (int j = 0; j < 10; j++) acc4[j] += W4[j * 16 + i];
    }
    unsigned om = 0;
    #pragma unroll
    for (int j = 0; j < 10; j++)
        if (acc4[j] >= 2.0f) om |= 1u << j;
    return om;
}

#define BT 256

__global__ __launch_bounds__(BT)
void snn_kernel(const float* __restrict__ x,
                const float* __restrict__ W2,
                const float* __restrict__ W3,
                const float* __restrict__ W4,
                float* __restrict__ out)
{
    __shared__ int sMp;

    const int tid = threadIdx.x;
    const size_t row = (size_t)blockIdx.x * BT + tid;

    // zero-fill this block's output tile: 2560 floats = 320 x 32B chunks.
    {
        ulonglong4* ov = reinterpret_cast<ulonglong4*>(out + (size_t)blockIdx.x * (BT * 10));
        const ulonglong4 z = make_ulonglong4(0ull, 0ull, 0ull, 0ull);
        ov[tid] = z;                       // chunks 0..255
        if (tid < 64) ov[tid + 256] = z;   // chunks 256..319
    }

    // warp 0 starts the W2 colmax scan early (coalesced; latency hidden under
    // its own layer-1 FMA block); published at the post-compute barrier.
    float cmx = 0.0f;
    if (tid < 32) {
        cmx = W2[tid];
        #pragma unroll
        for (int j = 1; j < 32; j++) cmx = fmaxf(cmx, W2[j * 32 + tid]);
    }

    // direct x reads
    const float* xr = x + row * 5;
    const float x0 = __ldg(xr + 0);
    const float x1 = __ldg(xr + 1);
    const float x2 = __ldg(xr + 2);
    const float x3 = __ldg(xr + 3);
    const float x4 = __ldg(xr + 4);

    // Layer 1: dense 32x5, weights from __constant__ via float4 (LDC.128).
    // Same mul->fma order as the reference-validated R2/R8/R9 kernels.
    unsigned mask1 = 0;
    const float4* cw4 = reinterpret_cast<const float4*>(cW1);
    #pragma unroll
    for (int c = 0; c < 8; c++) {
        float w[20];
        #pragma unroll
        for (int q = 0; q < 5; q++) {
            float4 t = cw4[c * 5 + q];
            w[q * 4 + 0] = t.x; w[q * 4 + 1] = t.y;
            w[q * 4 + 2] = t.z; w[q * 4 + 3] = t.w;
        }
        #pragma unroll
        for (int r = 0; r < 4; r++) {
            float a = w[r * 5 + 0] * x0;
            a = fmaf(w[r * 5 + 1], x1, a);
            a = fmaf(w[r * 5 + 2], x2, a);
            a = fmaf(w[r * 5 + 3], x3, a);
            a = fmaf(w[r * 5 + 4], x4, a);
            if (a >= 2.0f) mask1 |= 1u << (4 * c + r);
        }
    }

    // warp 0 finishes minpop (shuffle-reduce + tiny scalar loop)
    if (tid < 32) {
        #pragma unroll
        for (int s = 16; s > 0; s >>= 1)
            cmx = fmaxf(cmx, __shfl_xor_sync(0xffffffffu, cmx, s));
        if (tid == 0) {
            int mp = 1;  // smallest popc whose bound popc*cmax could round to >= 2
            while (mp < 33 && (float)mp * cmx < 1.99f) mp++;
            sMp = mp;
        }
    }
    __syncthreads();   // publish sMp; order zero-fill STGs before rare scatter

    // gate (~1e-4 taken); rare path exact
    if (__popc(mask1) >= sMp) {
        unsigned om = rare_path(mask1, W2, W3, W4);
        if (om) {
            float* o = out + row * 10;
            #pragma unroll
            for (int j = 0; j < 10; j++)
                o[j] = ((om >> j) & 1u) ? 1.0f : 0.0f;
        }
    }
}

extern "C" void kernel_launch(void* const* d_in, const int* in_sizes, int n_in,
                              void* d_out, int out_size)
{
    const float* x  = (const float*)d_in[0];
    const float* W1 = (const float*)d_in[1];
    const float* W2 = (const float*)d_in[2];
    const float* W3 = (const float*)d_in[3];
    const float* W4 = (const float*)d_in[4];
    float* out = (float*)d_out;

    const int B = in_sizes[0] / 5;        // 2097152
    const int grid = B / BT;              // 8192

    cudaMemcpyToSymbolAsync(cW1, W1, 160 * sizeof(float), 0,
                            cudaMemcpyDeviceToDevice, 0);
    snn_kernel<<<grid, BT>>>(x, W2, W3, W4, out);
}